// round 1
// baseline (speedup 1.0000x reference)
#include <cuda_runtime.h>

#define EE 65536
#define NN 4096

// ---------------- device scratch (static, allocation-free) ----------------
__device__ double g_rsum, g_rsq;
__device__ double g_csum[128], g_csq[128];
__device__ float  g_bn1a[128], g_bn1c[128];
__device__ float  g_bn2a[128], g_bn2c[128];
__device__ float  g_y2[(size_t)EE * 128];   // per-edge hidden (4 pairs x 32)
__device__ int    g_cnt[NN];
__device__ float  g_acc0[NN * 16];
__device__ float  g_acc1[NN * 48];
__device__ float  g_S0[NN * 16];
__device__ float  g_S1[NN * 48];

// ---------------- zeroing (graph-replay safe) ----------------
__global__ void k_zero() {
    int i = blockIdx.x * blockDim.x + threadIdx.x;
    int stride = gridDim.x * blockDim.x;
    if (i == 0) { g_rsum = 0.0; g_rsq = 0.0; }
    if (i < 128) { g_csum[i] = 0.0; g_csq[i] = 0.0; }
    if (i < NN) g_cnt[i] = 0;
    for (int k = i; k < NN * 16; k += stride) g_acc0[k] = 0.f;
    for (int k = i; k < NN * 48; k += stride) g_acc1[k] = 0.f;
}

// ---------------- r statistics + in-degree count ----------------
__global__ void k_rstats(const float* __restrict__ r, const int* __restrict__ edst) {
    int i = blockIdx.x * blockDim.x + threadIdx.x;
    int stride = gridDim.x * blockDim.x;
    double s = 0.0, s2 = 0.0;
    for (int e = i; e < EE; e += stride) {
        double v = (double)r[e];
        s += v; s2 += v * v;
        atomicAdd(&g_cnt[edst[e]], 1);
    }
    for (int o = 16; o; o >>= 1) {
        s  += __shfl_down_sync(0xffffffffu, s, o);
        s2 += __shfl_down_sync(0xffffffffu, s2, o);
    }
    if ((threadIdx.x & 31) == 0) {
        atomicAdd(&g_rsum, s);
        atomicAdd(&g_rsq, s2);
    }
}

// ---------------- BN1 coefficients (analytic: layer1 input is scalar r) ----------------
__global__ void k_bn1(const float* __restrict__ rw1, const float* __restrict__ rg1,
                      const float* __restrict__ rbe1) {
    int c = threadIdx.x;  // 0..127 = pair*32 + j
    double mean = g_rsum / (double)EE;
    double var  = g_rsq / (double)EE - mean * mean;
    double w = (double)rw1[c], g = (double)rg1[c], be = (double)rbe1[c];
    double inv = 1.0 / sqrt(var * w * w + 1e-5);
    double a = w * inv * g;
    g_bn1a[c] = (float)a;
    g_bn1c[c] = (float)(be - mean * a);
}

// ---------------- y2 = relu(bn1(...)) @ w2 + b2 (per edge, 4 pairs) ----------------
__global__ __launch_bounds__(256) void k_y2(const float* __restrict__ r,
                                            const float* __restrict__ rw2,
                                            const float* __restrict__ rb2) {
    __shared__ float w2s[4096];
    __shared__ float b2s[128], a1s[128], c1s[128];
    for (int i = threadIdx.x; i < 4096; i += 256) w2s[i] = rw2[i];
    if (threadIdx.x < 128) {
        b2s[threadIdx.x] = rb2[threadIdx.x];
        a1s[threadIdx.x] = g_bn1a[threadIdx.x];
        c1s[threadIdx.x] = g_bn1c[threadIdx.x];
    }
    __syncthreads();
    int e = blockIdx.x * 256 + threadIdx.x;
    if (e >= EE) return;
    float rr = r[e];
    for (int p = 0; p < 4; p++) {
        float z1[32];
#pragma unroll
        for (int j = 0; j < 32; j++)
            z1[j] = fmaxf(0.f, a1s[p * 32 + j] * rr + c1s[p * 32 + j]);
#pragma unroll
        for (int j4 = 0; j4 < 8; j4++) {
            float4 acc = *(const float4*)&b2s[p * 32 + j4 * 4];
#pragma unroll
            for (int c = 0; c < 32; c++) {
                float4 w = *(const float4*)&w2s[p * 1024 + c * 32 + j4 * 4];
                float zc = z1[c];
                acc.x += zc * w.x; acc.y += zc * w.y; acc.z += zc * w.z; acc.w += zc * w.w;
            }
            *(float4*)&g_y2[(size_t)e * 128 + p * 32 + j4 * 4] = acc;
        }
    }
}

// ---------------- BN2 per-channel statistics ----------------
__global__ void k_y2stats() {
    int c = threadIdx.x;  // 128 channels
    int e0 = blockIdx.x * 256;
    double s = 0.0, s2 = 0.0;
    for (int e = e0; e < e0 + 256; e++) {
        double v = (double)g_y2[(size_t)e * 128 + c];
        s += v; s2 += v * v;
    }
    atomicAdd(&g_csum[c], s);
    atomicAdd(&g_csq[c], s2);
}

__global__ void k_bn2(const float* __restrict__ rg2, const float* __restrict__ rbe2) {
    int c = threadIdx.x;
    double mean = g_csum[c] / (double)EE;
    double var  = g_csq[c] / (double)EE - mean * mean;
    double A = (double)rg2[c] / sqrt(var + 1e-5);
    g_bn2a[c] = (float)A;
    g_bn2c[c] = (float)((double)rbe2[c] - mean * A);
}

// ---------------- self-interaction precompute per node ----------------
__global__ void k_node(const float* __restrict__ h0, const float* __restrict__ h1,
                       const float* __restrict__ Ws0, const float* __restrict__ Ws1) {
    int idx = blockIdx.x * blockDim.x + threadIdx.x;  // n*16 + o
    if (idx >= NN * 16) return;
    int n = idx >> 4, o = idx & 15;
    float s0 = 0.f, s1a = 0.f, s1b = 0.f, s1c = 0.f;
#pragma unroll
    for (int i = 0; i < 16; i++) {
        float w0 = Ws0[o * 16 + i], w1 = Ws1[o * 16 + i];
        s0  += w0 * h0[n * 16 + i];
        s1a += w1 * h1[n * 48 + i * 3 + 0];
        s1b += w1 * h1[n * 48 + i * 3 + 1];
        s1c += w1 * h1[n * 48 + i * 3 + 2];
    }
    g_S0[idx] = s0;
    g_S1[idx * 3 + 0] = s1a;
    g_S1[idx * 3 + 1] = s1b;
    g_S1[idx * 3 + 2] = s1c;
}

// ---------------- main edge kernel helpers ----------------
__device__ __forceinline__ void load_z(float* z, int e, int p,
                                       const float* __restrict__ sa2,
                                       const float* __restrict__ sc2) {
#pragma unroll
    for (int c4 = 0; c4 < 8; c4++) {
        float4 y = *(const float4*)&g_y2[(size_t)e * 128 + p * 32 + c4 * 4];
        int b = p * 32 + c4 * 4;
        z[c4 * 4 + 0] = fmaxf(0.f, sa2[b + 0] * y.x + sc2[b + 0]);
        z[c4 * 4 + 1] = fmaxf(0.f, sa2[b + 1] * y.y + sc2[b + 1]);
        z[c4 * 4 + 2] = fmaxf(0.f, sa2[b + 2] * y.z + sc2[b + 2]);
        z[c4 * 4 + 3] = fmaxf(0.f, sa2[b + 3] * y.w + sc2[b + 3]);
    }
}

// one output channel of an nf=1 pair: R[o,:] = z@w3[:,o,:] + b3, then dot with hvec
__device__ __forceinline__ float pair_nf1_o(const float* z, const float* __restrict__ sw,
                                            const float* __restrict__ sb, int o,
                                            const float* hvec) {
    float acc[16];
#pragma unroll
    for (int i4 = 0; i4 < 4; i4++) {
        float4 b = *(const float4*)&sb[o * 16 + i4 * 4];
        acc[i4 * 4 + 0] = b.x; acc[i4 * 4 + 1] = b.y;
        acc[i4 * 4 + 2] = b.z; acc[i4 * 4 + 3] = b.w;
    }
#pragma unroll
    for (int c = 0; c < 32; c++) {
        float zc = z[c];
#pragma unroll
        for (int i4 = 0; i4 < 4; i4++) {
            float4 w = *(const float4*)&sw[c * 256 + o * 16 + i4 * 4];
            acc[i4 * 4 + 0] += zc * w.x; acc[i4 * 4 + 1] += zc * w.y;
            acc[i4 * 4 + 2] += zc * w.z; acc[i4 * 4 + 3] += zc * w.w;
        }
    }
    float t = 0.f;
#pragma unroll
    for (int i = 0; i < 16; i++) t += acc[i] * hvec[i];
    return t;
}

// one output channel of pair (1,1): R[o,i,f], contracted with h1s over i, then basis over (f,q)
__device__ __forceinline__ void pair11_o(const float* z, const float* __restrict__ s11,
                                         const float* __restrict__ sb11, int o,
                                         const float* h1s, const float* b11v, float* out3) {
    float acc[48];
#pragma unroll
    for (int j4 = 0; j4 < 12; j4++) {
        float4 b = *(const float4*)&sb11[o * 48 + j4 * 4];
        acc[j4 * 4 + 0] = b.x; acc[j4 * 4 + 1] = b.y;
        acc[j4 * 4 + 2] = b.z; acc[j4 * 4 + 3] = b.w;
    }
#pragma unroll
    for (int c = 0; c < 32; c++) {
        float zc = z[c];
#pragma unroll
        for (int j4 = 0; j4 < 12; j4++) {
            float4 w = *(const float4*)&s11[c * 768 + o * 48 + j4 * 4];
            acc[j4 * 4 + 0] += zc * w.x; acc[j4 * 4 + 1] += zc * w.y;
            acc[j4 * 4 + 2] += zc * w.z; acc[j4 * 4 + 3] += zc * w.w;
        }
    }
    // wfq[f,q] = sum_i R[o,i,f] * h1s[i,q]
    float wfq[9];
#pragma unroll
    for (int f = 0; f < 3; f++)
#pragma unroll
        for (int q = 0; q < 3; q++) {
            float t = 0.f;
#pragma unroll
            for (int i = 0; i < 16; i++) t += acc[i * 3 + f] * h1s[i * 3 + q];
            wfq[f * 3 + q] = t;
        }
    // out[p] = sum_{f,q} basis11[p,q,f] * wfq[f,q]
#pragma unroll
    for (int p = 0; p < 3; p++) {
        float t = 0.f;
#pragma unroll
        for (int f = 0; f < 3; f++)
#pragma unroll
            for (int q = 0; q < 3; q++)
                t += b11v[p * 9 + q * 3 + f] * wfq[f * 3 + q];
        out3[p] = t;
    }
}

// ---------------- main edge kernel ----------------
__global__ __launch_bounds__(256, 1) void k_edge(
    const float* __restrict__ h0, const float* __restrict__ h1,
    const float* __restrict__ bas00g, const float* __restrict__ bas01g,
    const float* __restrict__ bas10g, const float* __restrict__ bas11g,
    const float* __restrict__ w300, const float* __restrict__ b300,
    const float* __restrict__ w301, const float* __restrict__ b301,
    const float* __restrict__ w310, const float* __restrict__ b310,
    const float* __restrict__ w311, const float* __restrict__ b311,
    const int* __restrict__ esrc, const int* __restrict__ edst) {
    extern __shared__ float smem[];
    float* s00  = smem;               // 8192
    float* s01  = smem + 8192;        // 8192
    float* s10  = smem + 16384;       // 8192
    float* s11  = smem + 24576;       // 24576
    float* sb00 = smem + 49152;       // 256
    float* sb01 = smem + 49408;       // 256
    float* sb10 = smem + 49664;       // 256
    float* sb11 = smem + 49920;       // 768
    float* sa2  = smem + 50688;       // 128
    float* sc2  = smem + 50816;       // 128

    for (int i = threadIdx.x; i < 8192; i += 256) {
        s00[i] = w300[i]; s01[i] = w301[i]; s10[i] = w310[i];
    }
    for (int i = threadIdx.x; i < 24576; i += 256) s11[i] = w311[i];
    {
        int t = threadIdx.x;
        sb00[t] = b300[t]; sb01[t] = b301[t]; sb10[t] = b310[t];
        for (int i = t; i < 768; i += 256) sb11[i] = b311[i];
        if (t < 128) { sa2[t] = g_bn2a[t]; sc2[t] = g_bn2c[t]; }
    }
    __syncthreads();

    for (int e = blockIdx.x * blockDim.x + threadIdx.x; e < EE; e += gridDim.x * blockDim.x) {
        const int src = esrc[e], dst = edst[e];
        float h0s[16], h1s[48];
#pragma unroll
        for (int i = 0; i < 4; i++)
            *(float4*)&h0s[i * 4] = *(const float4*)(h0 + src * 16 + i * 4);
#pragma unroll
        for (int i = 0; i < 12; i++)
            *(float4*)&h1s[i * 4] = *(const float4*)(h1 + src * 48 + i * 4);

        const float b00v = bas00g[e];
        float b01v[3], b10v[3], b11v[27];
#pragma unroll
        for (int p = 0; p < 3; p++) { b01v[p] = bas01g[e * 3 + p]; b10v[p] = bas10g[e * 3 + p]; }
#pragma unroll
        for (int k = 0; k < 27; k++) b11v[k] = bas11g[e * 27 + k];

        float hb[16];
#pragma unroll
        for (int i = 0; i < 16; i++)
            hb[i] = b10v[0] * h1s[i * 3] + b10v[1] * h1s[i * 3 + 1] + b10v[2] * h1s[i * 3 + 2];

        float zA[32], zB[32];

        // ---- degree-0 output: pairs (0,0) and (1,0) ----
        load_z(zA, e, 0, sa2, sc2);
        load_z(zB, e, 2, sa2, sc2);
#pragma unroll 1
        for (int o = 0; o < 16; o++) {
            float t0 = pair_nf1_o(zA, s00, sb00, o, h0s);
            float t1 = pair_nf1_o(zB, s10, sb10, o, hb);
            atomicAdd(&g_acc0[dst * 16 + o], b00v * t0 + t1);
        }

        // ---- degree-1 output: pairs (0,1) and (1,1) ----
        load_z(zA, e, 1, sa2, sc2);
        load_z(zB, e, 3, sa2, sc2);
#pragma unroll 1
        for (int o = 0; o < 16; o++) {
            float t01 = pair_nf1_o(zA, s01, sb01, o, h0s);
            float m3[3];
            pair11_o(zB, s11, sb11, o, h1s, b11v, m3);
            atomicAdd(&g_acc1[dst * 48 + o * 3 + 0], b01v[0] * t01 + m3[0]);
            atomicAdd(&g_acc1[dst * 48 + o * 3 + 1], b01v[1] * t01 + m3[1]);
            atomicAdd(&g_acc1[dst * 48 + o * 3 + 2], b01v[2] * t01 + m3[2]);
        }
    }
}

// ---------------- final: scatter-mean + self term ----------------
__global__ void k_final(float* __restrict__ out) {
    int i = blockIdx.x * blockDim.x + threadIdx.x;
    if (i < NN * 16) {
        int n = i >> 4;
        int c = g_cnt[n];
        float inv = 1.f / (float)(c > 0 ? c : 1);
        out[i] = g_acc0[i] * inv + (c > 0 ? g_S0[i] : 0.f);
    } else if (i < NN * 16 + NN * 48) {
        int j = i - NN * 16;
        int n = j / 48;
        int c = g_cnt[n];
        float inv = 1.f / (float)(c > 0 ? c : 1);
        out[i] = g_acc1[j] * inv + (c > 0 ? g_S1[j] : 0.f);
    }
}

// ---------------- launch ----------------
extern "C" void kernel_launch(void* const* d_in, const int* in_sizes, int n_in,
                              void* d_out, int out_size) {
    const float* h0   = (const float*)d_in[0];
    const float* h1   = (const float*)d_in[1];
    const float* r    = (const float*)d_in[2];
    const float* b00  = (const float*)d_in[3];
    const float* b01  = (const float*)d_in[4];
    const float* b10  = (const float*)d_in[5];
    const float* b11  = (const float*)d_in[6];
    const float* rw1  = (const float*)d_in[7];
    // d_in[8] = rb1 (cancels in BN1)
    const float* rg1  = (const float*)d_in[9];
    const float* rbe1 = (const float*)d_in[10];
    const float* rw2  = (const float*)d_in[11];
    const float* rb2  = (const float*)d_in[12];
    const float* rg2  = (const float*)d_in[13];
    const float* rbe2 = (const float*)d_in[14];
    const float* w300 = (const float*)d_in[15];
    const float* b300 = (const float*)d_in[16];
    const float* w301 = (const float*)d_in[17];
    const float* b301 = (const float*)d_in[18];
    const float* w310 = (const float*)d_in[19];
    const float* b310 = (const float*)d_in[20];
    const float* w311 = (const float*)d_in[21];
    const float* b311 = (const float*)d_in[22];
    const float* Ws0  = (const float*)d_in[23];
    const float* Ws1  = (const float*)d_in[24];
    const int* esrc   = (const int*)d_in[25];
    const int* edst   = (const int*)d_in[26];
    float* out = (float*)d_out;

    const int smem_bytes = 50944 * 4;  // 203,776 B
    cudaFuncSetAttribute(k_edge, cudaFuncAttributeMaxDynamicSharedMemorySize, smem_bytes);

    k_zero<<<256, 256>>>();
    k_rstats<<<256, 256>>>(r, edst);
    k_bn1<<<1, 128>>>(rw1, rg1, rbe1);
    k_y2<<<256, 256>>>(r, rw2, rb2);
    k_y2stats<<<256, 128>>>();
    k_bn2<<<1, 128>>>(rg2, rbe2);
    k_node<<<256, 256>>>(h0, h1, Ws0, Ws1);
    k_edge<<<148, 256, smem_bytes>>>(h0, h1, b00, b01, b10, b11,
                                     w300, b300, w301, b301, w310, b310, w311, b311,
                                     esrc, edst);
    k_final<<<1024, 256>>>(out);
}